// round 16
// baseline (speedup 1.0000x reference)
#include <cuda_runtime.h>
#include <cuda_bf16.h>
#include <cuda_fp16.h>
#include <stdint.h>
#include <math.h>

#define NN 50000
#define NE 800000
#define DD 128
#define NT_NODE 391
#define NT_EDGE 6250
#define EGRID 148

// ---------------- device scratch ---------------------------------------------
__device__ float  g_Ah[NN*DD];
__device__ __half g_Bhh[NN*DD];
__device__ __half g_Dhh[NN*DD];
__device__ __half g_Ehh[NN*DD];
__device__ __half g_Ce[(size_t)NE*DD];
__device__ __half g_xh[(size_t)NE*DD];
__device__ float  g_hnew[NN*DD];
__device__ int    g_deg[NN];
__device__ int    g_off[NN+1];
__device__ int    g_cur[NN];
__device__ int2   g_perm[NE];
__device__ float  g_sum_e[DD], g_sumsq_e[DD], g_sum_h[DD], g_sumsq_h[DD];
__device__ int    g_bsum[64], g_boff[64];
__device__ float  g_slab[2][64][DD];
__device__ float  g_slabh[2][64][DD];
__device__ __nv_bfloat16 g_WHi[5*16384];
__device__ __nv_bfloat16 g_WLo[5*16384];

#define SM_BIAS 0
#define SM_WHI  512
#define SM_WLO  35328
#define SM_A0   70144
#define SM_A1   137728
#define SM_EDGE_TOTAL 205312
#define SM_NODE_TOTAL 137728
#define RS  68
#define RSF 132

__device__ __forceinline__ void mma16816(float* c, const uint32_t* a, const uint32_t* b) {
    asm volatile("mma.sync.aligned.m16n8k16.row.col.f32.bf16.bf16.f32 "
        "{%0,%1,%2,%3}, {%4,%5,%6,%7}, {%8,%9}, {%0,%1,%2,%3};"
        : "+f"(c[0]), "+f"(c[1]), "+f"(c[2]), "+f"(c[3])
        : "r"(a[0]), "r"(a[1]), "r"(a[2]), "r"(a[3]), "r"(b[0]), "r"(b[1]));
}

__device__ __forceinline__ uint32_t smem_u32(const void* p) {
    uint32_t a;
    asm("{ .reg .u64 t; cvta.to.shared.u64 t, %1; cvt.u32.u64 %0, t; }" : "=r"(a) : "l"(p));
    return a;
}

__device__ __forceinline__ void split2(float2 v, uint32_t& hi, uint32_t& lo) {
    __nv_bfloat162 h = __floats2bfloat162_rn(v.x, v.y);
    float hx = __bfloat162float(__low2bfloat16(h));
    float hy = __bfloat162float(__high2bfloat16(h));
    __nv_bfloat162 l = __floats2bfloat162_rn(v.x - hx, v.y - hy);
    hi = *(uint32_t*)&h; lo = *(uint32_t*)&l;
}

// ---------------- small kernels -----------------------------------------------
__global__ void k_init() {
    int i = blockIdx.x * 256 + threadIdx.x;
    if (i < NN) g_deg[i] = 0;
    if (i < DD) { g_sum_e[i] = 0.f; g_sumsq_e[i] = 0.f; g_sum_h[i] = 0.f; g_sumsq_h[i] = 0.f; }
    if (i < 2*64*DD) { ((float*)g_slab)[i] = 0.f; ((float*)g_slabh)[i] = 0.f; }
}

__global__ void k_deg(const int* __restrict__ dst) {
    int i = blockIdx.x * 256 + threadIdx.x;
    if (i < NE) atomicAdd(&g_deg[dst[i]], 1);
}

__global__ void k_prep_w(const float* __restrict__ WA, const float* __restrict__ WB,
                         const float* __restrict__ WC, const float* __restrict__ WD,
                         const float* __restrict__ WE) {
    const float* Ws[5] = {WA, WB, WC, WD, WE};
    int mat = blockIdx.y;
    int i = blockIdx.x * 256 + threadIdx.x;
    int n = i >> 7, k = i & 127;
    float x = Ws[mat][k * 128 + n];
    __nv_bfloat16 hb = __float2bfloat16(x);
    __nv_bfloat16 lb = __float2bfloat16(x - __bfloat162float(hb));
    g_WHi[mat * 16384 + i] = hb;
    g_WLo[mat * 16384 + i] = lb;
}

template<int NT>
__device__ __forceinline__ void load_w(char* sm_, int mat, const float* __restrict__ bias, int t) {
    const uint4* wh = (const uint4*)(g_WHi + mat * 16384);
    const uint4* wl = (const uint4*)(g_WLo + mat * 16384);
    __nv_bfloat16* dh = (__nv_bfloat16*)(sm_ + SM_WHI);
    __nv_bfloat16* dl = (__nv_bfloat16*)(sm_ + SM_WLO);
    #pragma unroll
    for (int i = t; i < 2048; i += NT) {
        int n = i >> 4, kg = i & 15;
        *(uint4*)(dh + n * 136 + kg * 8) = wh[i];
        *(uint4*)(dl + n * 136 + kg * 8) = wl[i];
    }
    if (t < 128) ((float*)(sm_ + SM_BIAS))[t] = bias[t];
}

// ---------------- 3-term compute from f32 A smem -------------------------------
__device__ __forceinline__ void compute_f32(const float* __restrict__ aF, const char* sm_,
                                            float acc[2][4][4], int rm, int cn, int lane) {
    #pragma unroll
    for (int mt = 0; mt < 2; mt++)
        #pragma unroll
        for (int nt = 0; nt < 4; nt++)
            #pragma unroll
            for (int q = 0; q < 4; q++) acc[mt][nt][q] = 0.f;
    const uint32_t* wHi = (const uint32_t*)(sm_ + SM_WHI);
    const uint32_t* wLo = (const uint32_t*)(sm_ + SM_WLO);
    int g = lane >> 2, tq = lane & 3;
    #pragma unroll
    for (int s = 0; s < 8; s++) {
        uint32_t bH[4][2], bL[4][2];
        #pragma unroll
        for (int nt = 0; nt < 4; nt++) {
            const uint32_t* p = wHi + (cn + nt * 8 + g) * RS + s * 8 + tq;
            bH[nt][0] = p[0]; bH[nt][1] = p[4];
            const uint32_t* q = wLo + (cn + nt * 8 + g) * RS + s * 8 + tq;
            bL[nt][0] = q[0]; bL[nt][1] = q[4];
        }
        #pragma unroll
        for (int mt = 0; mt < 2; mt++) {
            const float* base = aF + (rm + mt * 16 + g) * RSF + s * 16 + 2 * tq;
            float2 q0 = *(const float2*)(base);
            float2 q1 = *(const float2*)(base + 8 * RSF);
            float2 q2 = *(const float2*)(base + 8);
            float2 q3 = *(const float2*)(base + 8 * RSF + 8);
            uint32_t aH[4], aL[4];
            split2(q0, aH[0], aL[0]);
            split2(q1, aH[1], aL[1]);
            split2(q2, aH[2], aL[2]);
            split2(q3, aH[3], aL[3]);
            #pragma unroll
            for (int nt = 0; nt < 4; nt++) {
                mma16816(acc[mt][nt], aH, bH[nt]);
                mma16816(acc[mt][nt], aH, bL[nt]);
                mma16816(acc[mt][nt], aL, bH[nt]);
            }
        }
    }
}

// ---------------- node GEMM: Ah(f32), Bh/Dh/Eh(f16) ----------------------------
__global__ void __launch_bounds__(512, 1) k_node_hmma(
    const float* __restrict__ h,
    const float* __restrict__ bA, const float* __restrict__ bB,
    const float* __restrict__ bD, const float* __restrict__ bE)
{
    extern __shared__ char sm_[];
    const int t = threadIdx.x, lane = t & 31, w = t >> 5;
    const int rm = (w & 3) * 32, cn = (w >> 2) * 32;
    const int rowBase = blockIdx.x * 128;
    const float* sBias = (const float*)(sm_ + SM_BIAS);
    float* aF = (float*)(sm_ + SM_A0);

    #pragma unroll
    for (int i = 0; i < 8; i++) {
        int idx = t + i * 512;
        int r = idx >> 5, cg = (idx & 31) << 2;
        float4 x = (rowBase + r >= NN) ? make_float4(0.f, 0.f, 0.f, 0.f)
                 : *(const float4*)(h + (size_t)(rowBase + r) * DD + cg);
        *(float4*)(aF + r * RSF + cg) = x;
    }

    const float* const biases[4] = {bA, bB, bD, bE};
    const int img[4] = {0, 1, 3, 4};

    for (int mat = 0; mat < 4; mat++) {
        __syncthreads();
        load_w<512>(sm_, img[mat], biases[mat], t);
        __syncthreads();
        float acc[2][4][4];
        compute_f32(aF, sm_, acc, rm, cn, lane);
        int g = lane >> 2, tq = lane & 3;
        #pragma unroll
        for (int mt = 0; mt < 2; mt++) {
            #pragma unroll
            for (int half = 0; half < 2; half++) {
                int row = rowBase + rm + mt * 16 + half * 8 + g;
                if (row < NN) {
                    #pragma unroll
                    for (int nt = 0; nt < 4; nt++) {
                        int col = cn + nt * 8 + tq * 2;
                        float vx = acc[mt][nt][half * 2 + 0] + sBias[col];
                        float vy = acc[mt][nt][half * 2 + 1] + sBias[col + 1];
                        if (mat == 0) {
                            *(float2*)(g_Ah + (size_t)row * DD + col) = make_float2(vx, vy);
                        } else {
                            __half* dst = (mat == 1 ? g_Bhh : (mat == 2 ? g_Dhh : g_Ehh))
                                          + (size_t)row * DD + col;
                            *(__half2*)dst = __floats2half2_rn(vx, vy);
                        }
                    }
                }
            }
        }
    }
}

// ---------------- edge GEMM: 512 thr, cp.async double-buffered (R13) -----------
__device__ __forceinline__ void issue_tile(const float* __restrict__ e, int tile,
                                           uint32_t sdst, int t) {
    const char* gsrc = (const char*)(e + (size_t)tile * 128 * DD);
    #pragma unroll
    for (int i = 0; i < 8; i++) {
        int idx = t + i * 512;
        int r = idx >> 5, c = idx & 31;
        uint32_t d = sdst + r * (RSF * 4) + c * 16;
        const char* gp = gsrc + r * 512 + c * 16;
        asm volatile("cp.async.cg.shared.global [%0], [%1], 16;" :: "r"(d), "l"(gp));
    }
    asm volatile("cp.async.commit_group;" ::: "memory");
}

__global__ void __launch_bounds__(512, 1) k_edge_hmma(
    const float* __restrict__ e, const float* __restrict__ bC)
{
    extern __shared__ char sm_[];
    const int t = threadIdx.x, lane = t & 31, w = t >> 5;
    const int rm = (w & 3) * 32, cn = (w >> 2) * 32;
    const float* sBias = (const float*)(sm_ + SM_BIAS);
    const uint32_t sA[2] = { smem_u32(sm_ + SM_A0), smem_u32(sm_ + SM_A1) };

    load_w<512>(sm_, 2, bC, t);

    int tile = blockIdx.x;
    if (tile < NT_EDGE) issue_tile(e, tile, sA[0], t);

    int par = 0;
    for (; tile < NT_EDGE; tile += EGRID) {
        int nextTile = tile + EGRID;
        bool hasNext = nextTile < NT_EDGE;
        if (hasNext) issue_tile(e, nextTile, sA[par ^ 1], t);
        if (hasNext) asm volatile("cp.async.wait_group 1;" ::: "memory");
        else         asm volatile("cp.async.wait_group 0;" ::: "memory");
        __syncthreads();

        float acc[2][4][4];
        compute_f32((const float*)(sm_ + (par ? SM_A1 : SM_A0)), sm_, acc, rm, cn, lane);

        {
            int g = lane >> 2, tq = lane & 3;
            int rowBase = tile * 128;
            #pragma unroll
            for (int mt = 0; mt < 2; mt++) {
                #pragma unroll
                for (int half = 0; half < 2; half++) {
                    int row = rowBase + rm + mt * 16 + half * 8 + g;
                    __half* op = g_Ce + (size_t)row * DD;
                    #pragma unroll
                    for (int nt = 0; nt < 4; nt++) {
                        int col = cn + nt * 8 + tq * 2;
                        __half2 hv = __floats2half2_rn(
                            acc[mt][nt][half * 2 + 0] + sBias[col],
                            acc[mt][nt][half * 2 + 1] + sBias[col + 1]);
                        *(__half2*)(op + col) = hv;
                    }
                }
            }
        }
        __syncthreads();
        par ^= 1;
    }
}

// ---------------- hierarchical scan -------------------------------------------
__global__ void k_scan1() {
    __shared__ int sbuf[1024];
    const int t = threadIdx.x;
    int gidx = blockIdx.x * 1024 + t;
    int v = (gidx < NN) ? g_deg[gidx] : 0;
    sbuf[t] = v;
    __syncthreads();
    for (int d = 1; d < 1024; d <<= 1) {
        int x = (t >= d) ? sbuf[t - d] : 0;
        __syncthreads();
        sbuf[t] += x;
        __syncthreads();
    }
    if (gidx < NN) g_off[gidx] = sbuf[t] - v;
    if (t == 1023) g_bsum[blockIdx.x] = sbuf[1023];
}
__global__ void k_scan2() {
    int a = 0;
    for (int b = 0; b < 49; b++) { g_boff[b] = a; a += g_bsum[b]; }
    g_off[NN] = a;
}
__global__ void k_scan3() {
    int gidx = blockIdx.x * 256 + threadIdx.x;
    if (gidx < NN) {
        int o = g_off[gidx] + g_boff[gidx >> 10];
        g_off[gidx] = o;
        g_cur[gidx] = o;
    }
}

__global__ void k_scatter(const int* __restrict__ src, const int* __restrict__ dst) {
    int i = blockIdx.x * 256 + threadIdx.x;
    if (i < NE) {
        int d = dst[i];
        int pos = atomicAdd(&g_cur[d], 1);
        g_perm[pos] = make_int2(i, src[i]);
    }
}

// ---------------- k_msg: edge-parallel x = Ce + Dh[src] + Eh[dst] + e-stats ----
__global__ void __launch_bounds__(256) k_msg(const int* __restrict__ src,
                                             const int* __restrict__ dst) {
    const int t = threadIdx.x, w = t >> 5, lane = t & 31;
    float es[4] = {0.f, 0.f, 0.f, 0.f}, esq[4] = {0.f, 0.f, 0.f, 0.f};
    for (int eg = blockIdx.x * 8 + w; eg < NE; eg += gridDim.x * 8) {
        int s = src[eg], d = dst[eg];
        uint2 cu = *(const uint2*)(g_Ce  + (size_t)eg * DD + lane * 4);
        uint2 du = *(const uint2*)(g_Dhh + (size_t)s  * DD + lane * 4);
        uint2 eu = *(const uint2*)(g_Ehh + (size_t)d  * DD + lane * 4);
        float2 c0 = __half22float2(*(__half2*)&cu.x), c1 = __half22float2(*(__half2*)&cu.y);
        float2 d0 = __half22float2(*(__half2*)&du.x), d1 = __half22float2(*(__half2*)&du.y);
        float2 e0 = __half22float2(*(__half2*)&eu.x), e1 = __half22float2(*(__half2*)&eu.y);
        float x0 = c0.x + d0.x + e0.x;
        float x1 = c0.y + d0.y + e0.y;
        float x2 = c1.x + d1.x + e1.x;
        float x3 = c1.y + d1.y + e1.y;
        __half2 h0 = __floats2half2_rn(x0, x1);
        __half2 h1 = __floats2half2_rn(x2, x3);
        uint2 ou; ou.x = *(uint32_t*)&h0; ou.y = *(uint32_t*)&h1;
        *(uint2*)(g_xh + (size_t)eg * DD + lane * 4) = ou;
        es[0] += x0; es[1] += x1; es[2] += x2; es[3] += x3;
        esq[0] = fmaf(x0, x0, esq[0]); esq[1] = fmaf(x1, x1, esq[1]);
        esq[2] = fmaf(x2, x2, esq[2]); esq[3] = fmaf(x3, x3, esq[3]);
    }
    int sl = blockIdx.x & 63;
    #pragma unroll
    for (int q = 0; q < 4; q++) {
        atomicAdd(&g_slab[0][sl][lane * 4 + q], es[q]);
        atomicAdd(&g_slab[1][sl][lane * 4 + q], esq[q]);
    }
}

// ---------------- k_agg: node-parallel num/den + h_new + h-stats ---------------
__global__ void k_agg() {
    const int n = blockIdx.x;
    const int t = threadIdx.x;
    const int s0 = g_off[n], s1 = g_off[n + 1];
    float num = 0.f, den = 0.f;
    int j = s0;
    for (; j + 2 <= s1; j += 2) {
        int2 p0 = g_perm[j], p1 = g_perm[j + 1];
        float x0 = __half2float(g_xh[(size_t)p0.x * DD + t]);
        float x1 = __half2float(g_xh[(size_t)p1.x * DD + t]);
        float b0 = __half2float(g_Bhh[(size_t)p0.y * DD + t]);
        float b1 = __half2float(g_Bhh[(size_t)p1.y * DD + t]);
        float sg0 = 1.f / (1.f + __expf(-x0));
        float sg1 = 1.f / (1.f + __expf(-x1));
        num = fmaf(sg0, b0, num); num = fmaf(sg1, b1, num);
        den += sg0 + sg1;
    }
    if (j < s1) {
        int2 p = g_perm[j];
        float x = __half2float(g_xh[(size_t)p.x * DD + t]);
        float sg = 1.f / (1.f + __expf(-x));
        num = fmaf(sg, __half2float(g_Bhh[(size_t)p.y * DD + t]), num);
        den += sg;
    }
    float hn = g_Ah[(size_t)n * DD + t] + num / (den + 1e-6f);
    g_hnew[(size_t)n * DD + t] = hn;
    int sl = n & 63;
    atomicAdd(&g_slabh[0][sl][t], hn);
    atomicAdd(&g_slabh[1][sl][t], hn * hn);
}

__global__ void k_red_e() {
    int t = threadIdx.x;
    float a = 0.f, b = 0.f;
    for (int j = 0; j < 64; j++) { a += g_slab[0][j][t]; b += g_slab[1][j][t]; }
    g_sum_e[t] = a; g_sumsq_e[t] = b;
}
__global__ void k_red_h() {
    int t = threadIdx.x;
    float a = 0.f, b = 0.f;
    for (int j = 0; j < 64; j++) { a += g_slabh[0][j][t]; b += g_slabh[1][j][t]; }
    g_sum_h[t] = a; g_sumsq_h[t] = b;
}

// ---------------- outputs ------------------------------------------------------
__global__ void k_hout(const float* __restrict__ gamma, const float* __restrict__ beta,
                       float* __restrict__ out) {
    __shared__ float sM[DD], sS[DD], sB[DD];
    const int t = threadIdx.x;
    if (t < DD) {
        float mean = g_sum_h[t] * (1.f / NN);
        float var  = g_sumsq_h[t] * (1.f / NN) - mean * mean;
        sM[t] = mean; sS[t] = gamma[t] * rsqrtf(var + 1e-5f); sB[t] = beta[t];
    }
    __syncthreads();
    int i4 = blockIdx.x * 256 + t;
    if (i4 < NN * 32) {
        float4 x = ((const float4*)g_hnew)[i4];
        int c = (i4 & 31) * 4;
        float4 o;
        o.x = fmaxf(0.f, (x.x - sM[c+0]) * sS[c+0] + sB[c+0]);
        o.y = fmaxf(0.f, (x.y - sM[c+1]) * sS[c+1] + sB[c+1]);
        o.z = fmaxf(0.f, (x.z - sM[c+2]) * sS[c+2] + sB[c+2]);
        o.w = fmaxf(0.f, (x.w - sM[c+3]) * sS[c+3] + sB[c+3]);
        __stcs(&((float4*)out)[i4], o);
    }
}

__global__ void k_eout(const float* __restrict__ gamma, const float* __restrict__ beta,
                       float* __restrict__ out) {
    __shared__ float sM[DD], sS[DD], sB[DD];
    const int t = threadIdx.x;
    if (t < DD) {
        float mean = g_sum_e[t] * (1.f / NE);
        float var  = g_sumsq_e[t] * (1.f / NE) - mean * mean;
        sM[t] = mean; sS[t] = gamma[t] * rsqrtf(var + 1e-5f); sB[t] = beta[t];
    }
    __syncthreads();
    size_t i8 = (size_t)blockIdx.x * 256 + t;
    const __half2* xp = (const __half2*)(g_xh + i8 * 8);
    int c = (int)((i8 & 15) * 8);
    float* op = out + i8 * 8;
    float4 o0, o1;
    float2 v0 = __half22float2(__ldcs(&xp[0]));
    float2 v1 = __half22float2(__ldcs(&xp[1]));
    float2 v2 = __half22float2(__ldcs(&xp[2]));
    float2 v3 = __half22float2(__ldcs(&xp[3]));
    o0.x = fmaxf(0.f, (v0.x - sM[c+0]) * sS[c+0] + sB[c+0]);
    o0.y = fmaxf(0.f, (v0.y - sM[c+1]) * sS[c+1] + sB[c+1]);
    o0.z = fmaxf(0.f, (v1.x - sM[c+2]) * sS[c+2] + sB[c+2]);
    o0.w = fmaxf(0.f, (v1.y - sM[c+3]) * sS[c+3] + sB[c+3]);
    o1.x = fmaxf(0.f, (v2.x - sM[c+4]) * sS[c+4] + sB[c+4]);
    o1.y = fmaxf(0.f, (v2.y - sM[c+5]) * sS[c+5] + sB[c+5]);
    o1.z = fmaxf(0.f, (v3.x - sM[c+6]) * sS[c+6] + sB[c+6]);
    o1.w = fmaxf(0.f, (v3.y - sM[c+7]) * sS[c+7] + sB[c+7]);
    __stcs((float4*)(op), o0);
    __stcs((float4*)(op + 4), o1);
}

// ---------------- launch ------------------------------------------------------
extern "C" void kernel_launch(void* const* d_in, const int* in_sizes, int n_in,
                              void* d_out, int out_size) {
    const float* h   = (const float*)d_in[0];
    const float* e   = (const float*)d_in[1];
    const int*   src = (const int*)  d_in[2];
    const int*   dst = (const int*)  d_in[3];
    const float* WA  = (const float*)d_in[4];  const float* bA = (const float*)d_in[5];
    const float* WB  = (const float*)d_in[6];  const float* bB = (const float*)d_in[7];
    const float* WC  = (const float*)d_in[8];  const float* bC = (const float*)d_in[9];
    const float* WD  = (const float*)d_in[10]; const float* bD = (const float*)d_in[11];
    const float* WE  = (const float*)d_in[12]; const float* bE = (const float*)d_in[13];
    const float* gamma_h = (const float*)d_in[14]; const float* beta_h = (const float*)d_in[15];
    const float* gamma_e = (const float*)d_in[16]; const float* beta_e = (const float*)d_in[17];
    float* out = (float*)d_out;

    static cudaStream_t s1 = nullptr;
    static cudaEvent_t ev0 = nullptr, ev1 = nullptr, ev2 = nullptr, ev3 = nullptr;
    if (!s1) {
        cudaStreamCreateWithFlags(&s1, cudaStreamNonBlocking);
        cudaEventCreateWithFlags(&ev0, cudaEventDisableTiming);
        cudaEventCreateWithFlags(&ev1, cudaEventDisableTiming);
        cudaEventCreateWithFlags(&ev2, cudaEventDisableTiming);
        cudaEventCreateWithFlags(&ev3, cudaEventDisableTiming);
        cudaFuncSetAttribute(k_node_hmma, cudaFuncAttributeMaxDynamicSharedMemorySize, SM_NODE_TOTAL);
        cudaFuncSetAttribute(k_edge_hmma, cudaFuncAttributeMaxDynamicSharedMemorySize, SM_EDGE_TOTAL);
    }

    // k_edge_hmma stays 4th submitted (ncu capture slot)
    k_init<<<(NN + 255) / 256, 256>>>();                                   // 1
    k_prep_w<<<dim3(64, 5), 256>>>(WA, WB, WC, WD, WE);                    // 2
    cudaEventRecord(ev0, 0);
    cudaStreamWaitEvent(s1, ev0, 0);
    k_deg<<<(NE + 255) / 256, 256, 0, s1>>>(dst);                          // 3
    k_edge_hmma<<<EGRID, 512, SM_EDGE_TOTAL>>>(e, bC);                     // 4 <- profiled
    k_scan1<<<49, 1024, 0, s1>>>();
    k_scan2<<<1, 1, 0, s1>>>();
    k_scan3<<<(NN + 255) / 256, 256, 0, s1>>>();
    k_scatter<<<(NE + 255) / 256, 256, 0, s1>>>(src, dst);
    k_node_hmma<<<NT_NODE, 512, SM_NODE_TOTAL, s1>>>(h, bA, bB, bD, bE);
    cudaEventRecord(ev1, s1);

    cudaStreamWaitEvent(0, ev1, 0);                // join: Ce + Dh/Eh ready
    k_msg<<<2000, 256>>>(src, dst);
    k_red_e<<<1, 128>>>();
    cudaEventRecord(ev2, 0);

    // side: CSR aggregation + h output, overlapping with eout on main
    cudaStreamWaitEvent(s1, ev2, 0);
    k_agg<<<NN, 128, 0, s1>>>();
    k_red_h<<<1, 128, 0, s1>>>();
    k_hout<<<(NN * 32 + 255) / 256, 256, 0, s1>>>(gamma_h, beta_h, out);
    cudaEventRecord(ev3, s1);

    k_eout<<<NE / 16, 256>>>(gamma_e, beta_e, out + (size_t)NN * DD);
    cudaStreamWaitEvent(0, ev3, 0);
}

// round 17
// speedup vs baseline: 1.4492x; 1.4492x over previous
#include <cuda_runtime.h>
#include <cuda_fp16.h>
#include <stdint.h>
#include <math.h>

#define NN 50000
#define NE 800000
#define DD 128
#define NT_NODE 391
#define NT_EDGE 6250
#define EGRID 148

// ---------------- device scratch ---------------------------------------------
__device__ float  g_Ah[NN*DD];
__device__ __half g_Bhh[NN*DD];
__device__ __half g_Dhh[NN*DD];
__device__ float  g_Eh[NN*DD];
__device__ __half g_Ce[(size_t)NE*DD];
__device__ __half g_xh[(size_t)NE*DD];
__device__ float  g_hnew[NN*DD];
__device__ int    g_deg[NN];
__device__ int    g_off[NN+1];
__device__ int    g_cur[NN];
__device__ int2   g_perm[NE];
__device__ float  g_sum_e[DD], g_sumsq_e[DD], g_sum_h[DD], g_sumsq_h[DD];
__device__ int    g_bsum[64], g_boff[64];
__device__ float  g_slab[2][64][DD];
__device__ float  g_slabh[2][64][DD];
__device__ __half g_WH[5*16384];          // W^T fp16, n-major

// smem layout (bytes): bias | W fp16 (padded) | A fp16 buffers (rows 136 halfs)
#define SM_BIAS 0
#define SM_W    512
#define SM_A0   35328
#define SM_A1   70144
#define SM_EDGE_TOTAL 104960
#define SM_NODE_TOTAL 70144
#define RS 68   // row stride in 32-bit words (136 halfs)

__device__ __forceinline__ void mma_fp16(float* c, const uint32_t* a, const uint32_t* b) {
    asm volatile("mma.sync.aligned.m16n8k16.row.col.f32.f16.f16.f32 "
        "{%0,%1,%2,%3}, {%4,%5,%6,%7}, {%8,%9}, {%0,%1,%2,%3};"
        : "+f"(c[0]), "+f"(c[1]), "+f"(c[2]), "+f"(c[3])
        : "r"(a[0]), "r"(a[1]), "r"(a[2]), "r"(a[3]), "r"(b[0]), "r"(b[1]));
}

// ---------------- small kernels -----------------------------------------------
__global__ void k_init() {
    int i = blockIdx.x * 256 + threadIdx.x;
    if (i < NN) g_deg[i] = 0;
    if (i < DD) { g_sum_e[i] = 0.f; g_sumsq_e[i] = 0.f; g_sum_h[i] = 0.f; g_sumsq_h[i] = 0.f; }
    if (i < 2*64*DD) { ((float*)g_slab)[i] = 0.f; ((float*)g_slabh)[i] = 0.f; }
}

__global__ void k_deg(const int* __restrict__ dst) {
    int i = blockIdx.x * 256 + threadIdx.x;
    if (i < NE) atomicAdd(&g_deg[dst[i]], 1);
}

__global__ void k_prep_w(const float* __restrict__ WA, const float* __restrict__ WB,
                         const float* __restrict__ WC, const float* __restrict__ WD,
                         const float* __restrict__ WE) {
    const float* Ws[5] = {WA, WB, WC, WD, WE};
    int mat = blockIdx.y;
    int i = blockIdx.x * 256 + threadIdx.x;
    int n = i >> 7, k = i & 127;
    g_WH[mat * 16384 + i] = __float2half_rn(Ws[mat][k * 128 + n]);  // B[n][k] = W[k][n]
}

template<int NT>
__device__ __forceinline__ void load_w(char* sm_, int mat, const float* __restrict__ bias, int t) {
    const uint4* wh = (const uint4*)(g_WH + mat * 16384);
    __half* dh = (__half*)(sm_ + SM_W);
    #pragma unroll
    for (int i = t; i < 2048; i += NT) {
        int n = i >> 4, kg = i & 15;
        *(uint4*)(dh + n * 136 + kg * 8) = wh[i];
    }
    if (t < 128) ((float*)(sm_ + SM_BIAS))[t] = bias[t];
}

// ---------------- single-pass fp16 compute (warp tile 32x32) -------------------
__device__ __forceinline__ void compute_h(const uint32_t* __restrict__ sA,
                                          const uint32_t* __restrict__ sW,
                                          float acc[2][4][4], int rm, int cn, int lane) {
    #pragma unroll
    for (int mt = 0; mt < 2; mt++)
        #pragma unroll
        for (int nt = 0; nt < 4; nt++)
            #pragma unroll
            for (int q = 0; q < 4; q++) acc[mt][nt][q] = 0.f;
    int g = lane >> 2, tq = lane & 3;
    #pragma unroll
    for (int s = 0; s < 8; s++) {
        uint32_t b[4][2];
        #pragma unroll
        for (int nt = 0; nt < 4; nt++) {
            const uint32_t* p = sW + (cn + nt * 8 + g) * RS + s * 8 + tq;
            b[nt][0] = p[0]; b[nt][1] = p[4];
        }
        #pragma unroll
        for (int mt = 0; mt < 2; mt++) {
            const uint32_t* p0 = sA + (rm + mt * 16 + g) * RS + s * 8 + tq;
            const uint32_t* p1 = p0 + 8 * RS;
            uint32_t a[4];
            a[0] = p0[0]; a[1] = p1[0]; a[2] = p0[4]; a[3] = p1[4];
            #pragma unroll
            for (int nt = 0; nt < 4; nt++)
                mma_fp16(acc[mt][nt], a, b[nt]);
        }
    }
}

// convert float4 -> 2x half2, store 8B to padded fp16 smem row
__device__ __forceinline__ void cv_store(__half* sA, int r, int cg, float4 x) {
    __half2 h0 = __floats2half2_rn(x.x, x.y);
    __half2 h1 = __floats2half2_rn(x.z, x.w);
    uint2 u; u.x = *(uint32_t*)&h0; u.y = *(uint32_t*)&h1;
    *(uint2*)(sA + r * 136 + cg) = u;
}

// ---------------- node GEMM: Ah(f32), Bh(f16), Dh(f16), Eh(f32) ----------------
__global__ void __launch_bounds__(512, 1) k_node_hmma(
    const float* __restrict__ h,
    const float* __restrict__ bA, const float* __restrict__ bB,
    const float* __restrict__ bD, const float* __restrict__ bE)
{
    extern __shared__ char sm_[];
    const int t = threadIdx.x, lane = t & 31, w = t >> 5;
    const int rm = (w & 3) * 32, cn = (w >> 2) * 32;
    const int rowBase = blockIdx.x * 128;
    const float* sBias = (const float*)(sm_ + SM_BIAS);
    __half* aH = (__half*)(sm_ + SM_A0);

    #pragma unroll
    for (int i = 0; i < 8; i++) {
        int idx = t + i * 512;
        int r = idx >> 5, cg = (idx & 31) << 2;
        float4 x = (rowBase + r >= NN) ? make_float4(0.f, 0.f, 0.f, 0.f)
                 : *(const float4*)(h + (size_t)(rowBase + r) * DD + cg);
        cv_store(aH, r, cg, x);
    }

    const float* const biases[4] = {bA, bB, bD, bE};
    const int img[4] = {0, 1, 3, 4};

    for (int mat = 0; mat < 4; mat++) {
        __syncthreads();
        load_w<512>(sm_, img[mat], biases[mat], t);
        __syncthreads();
        float acc[2][4][4];
        compute_h((const uint32_t*)aH, (const uint32_t*)(sm_ + SM_W), acc, rm, cn, lane);
        int g = lane >> 2, tq = lane & 3;
        #pragma unroll
        for (int mt = 0; mt < 2; mt++) {
            #pragma unroll
            for (int half_ = 0; half_ < 2; half_++) {
                int row = rowBase + rm + mt * 16 + half_ * 8 + g;
                if (row < NN) {
                    #pragma unroll
                    for (int nt = 0; nt < 4; nt++) {
                        int col = cn + nt * 8 + tq * 2;
                        float vx = acc[mt][nt][half_ * 2 + 0] + sBias[col];
                        float vy = acc[mt][nt][half_ * 2 + 1] + sBias[col + 1];
                        if (mat == 0) {
                            *(float2*)(g_Ah + (size_t)row * DD + col) = make_float2(vx, vy);
                        } else if (mat == 3) {
                            *(float2*)(g_Eh + (size_t)row * DD + col) = make_float2(vx, vy);
                        } else {
                            __half* dst = (mat == 1 ? g_Bhh : g_Dhh) + (size_t)row * DD + col;
                            *(__half2*)dst = __floats2half2_rn(vx, vy);
                        }
                    }
                }
            }
        }
    }
}

// ---------------- edge GEMM: 512 thr, fp16 tiles, reg-prefetch double buffer ---
__global__ void __launch_bounds__(512, 1) k_edge_hmma(
    const float* __restrict__ e, const float* __restrict__ bC)
{
    extern __shared__ char sm_[];
    const int t = threadIdx.x, lane = t & 31, w = t >> 5;
    const int rm = (w & 3) * 32, cn = (w >> 2) * 32;
    const float* sBias = (const float*)(sm_ + SM_BIAS);
    const uint32_t* sW = (const uint32_t*)(sm_ + SM_W);

    load_w<512>(sm_, 2, bC, t);

    int tile = blockIdx.x;
    if (tile < NT_EDGE) {
        __half* aH = (__half*)(sm_ + SM_A0);
        #pragma unroll
        for (int i = 0; i < 8; i++) {
            int idx = t + i * 512;
            int r = idx >> 5, cg = (idx & 31) << 2;
            float4 x = *(const float4*)(e + (size_t)(tile * 128 + r) * DD + cg);
            cv_store(aH, r, cg, x);
        }
    }
    __syncthreads();

    int par = 0;
    for (; tile < NT_EDGE; tile += EGRID) {
        int nextTile = tile + EGRID;
        bool hasNext = nextTile < NT_EDGE;
        float4 pf[8];
        if (hasNext) {
            #pragma unroll
            for (int i = 0; i < 8; i++) {
                int idx = t + i * 512;
                pf[i] = *(const float4*)(e + (size_t)(nextTile * 128 + (idx >> 5)) * DD + ((idx & 31) << 2));
            }
        }
        float acc[2][4][4];
        compute_h((const uint32_t*)(sm_ + (par ? SM_A1 : SM_A0)), sW, acc, rm, cn, lane);

        {   // epilogue: bias + fp16 Ce store
            int g = lane >> 2, tq = lane & 3;
            int rowBase = tile * 128;
            #pragma unroll
            for (int mt = 0; mt < 2; mt++) {
                #pragma unroll
                for (int half_ = 0; half_ < 2; half_++) {
                    int row = rowBase + rm + mt * 16 + half_ * 8 + g;
                    __half* op = g_Ce + (size_t)row * DD;
                    #pragma unroll
                    for (int nt = 0; nt < 4; nt++) {
                        int col = cn + nt * 8 + tq * 2;
                        __half2 hv = __floats2half2_rn(
                            acc[mt][nt][half_ * 2 + 0] + sBias[col],
                            acc[mt][nt][half_ * 2 + 1] + sBias[col + 1]);
                        *(__half2*)(op + col) = hv;
                    }
                }
            }
        }
        if (hasNext) {
            __half* aH = (__half*)(sm_ + (par ? SM_A0 : SM_A1));
            #pragma unroll
            for (int i = 0; i < 8; i++) {
                int idx = t + i * 512;
                cv_store(aH, idx >> 5, (idx & 31) << 2, pf[i]);
            }
        }
        __syncthreads();
        par ^= 1;
    }
}

// ---------------- hierarchical scan -------------------------------------------
__global__ void k_scan1() {
    __shared__ int sbuf[1024];
    const int t = threadIdx.x;
    int gidx = blockIdx.x * 1024 + t;
    int v = (gidx < NN) ? g_deg[gidx] : 0;
    sbuf[t] = v;
    __syncthreads();
    for (int d = 1; d < 1024; d <<= 1) {
        int x = (t >= d) ? sbuf[t - d] : 0;
        __syncthreads();
        sbuf[t] += x;
        __syncthreads();
    }
    if (gidx < NN) g_off[gidx] = sbuf[t] - v;
    if (t == 1023) g_bsum[blockIdx.x] = sbuf[1023];
}
__global__ void k_scan2() {
    int a = 0;
    for (int b = 0; b < 49; b++) { g_boff[b] = a; a += g_bsum[b]; }
    g_off[NN] = a;
}
__global__ void k_scan3() {
    int gidx = blockIdx.x * 256 + threadIdx.x;
    if (gidx < NN) {
        int o = g_off[gidx] + g_boff[gidx >> 10];
        g_off[gidx] = o;
        g_cur[gidx] = o;
    }
}

__global__ void k_scatter(const int* __restrict__ src, const int* __restrict__ dst) {
    int i = blockIdx.x * 256 + threadIdx.x;
    if (i < NE) {
        int d = dst[i];
        int pos = atomicAdd(&g_cur[d], 1);
        g_perm[pos] = make_int2(i, src[i]);
    }
}

// ---------------- gather (R13): h_new + stats + fp16 x write -------------------
__global__ void k_gather() {
    const int n = blockIdx.x;
    const int t = threadIdx.x;
    const int s0 = g_off[n], s1 = g_off[n + 1];
    const float eh = g_Eh[(size_t)n * DD + t];
    float num = 0.f, den = 0.f, es = 0.f, esq = 0.f;
    int j = s0;
    for (; j + 2 <= s1; j += 2) {
        int2 p0 = g_perm[j], p1 = g_perm[j + 1];
        float c0 = __half2float(g_Ce[(size_t)p0.x * DD + t]);
        float c1 = __half2float(g_Ce[(size_t)p1.x * DD + t]);
        float d0 = __half2float(g_Dhh[(size_t)p0.y * DD + t]);
        float d1 = __half2float(g_Dhh[(size_t)p1.y * DD + t]);
        float b0 = __half2float(g_Bhh[(size_t)p0.y * DD + t]);
        float b1 = __half2float(g_Bhh[(size_t)p1.y * DD + t]);
        float x0 = c0 + d0 + eh, x1 = c1 + d1 + eh;
        g_xh[(size_t)p0.x * DD + t] = __float2half_rn(x0);
        g_xh[(size_t)p1.x * DD + t] = __float2half_rn(x1);
        float sg0 = 1.f / (1.f + __expf(-x0));
        float sg1 = 1.f / (1.f + __expf(-x1));
        num = fmaf(sg0, b0, num); num = fmaf(sg1, b1, num);
        den += sg0 + sg1;
        es += x0 + x1;
        esq = fmaf(x0, x0, esq); esq = fmaf(x1, x1, esq);
    }
    if (j < s1) {
        int2 p = g_perm[j];
        float x = __half2float(g_Ce[(size_t)p.x * DD + t])
                + __half2float(g_Dhh[(size_t)p.y * DD + t]) + eh;
        g_xh[(size_t)p.x * DD + t] = __float2half_rn(x);
        float sg = 1.f / (1.f + __expf(-x));
        num = fmaf(sg, __half2float(g_Bhh[(size_t)p.y * DD + t]), num);
        den += sg;
        es += x; esq = fmaf(x, x, esq);
    }
    float hn = g_Ah[(size_t)n * DD + t] + num / (den + 1e-6f);
    g_hnew[(size_t)n * DD + t] = hn;
    int sl = n & 63;
    atomicAdd(&g_slab[0][sl][t], es);
    atomicAdd(&g_slab[1][sl][t], esq);
    atomicAdd(&g_slabh[0][sl][t], hn);
    atomicAdd(&g_slabh[1][sl][t], hn * hn);
}

__global__ void k_red() {
    int t = threadIdx.x;
    if (t < 128) {
        float a = 0.f, b = 0.f;
        for (int j = 0; j < 64; j++) { a += g_slab[0][j][t]; b += g_slab[1][j][t]; }
        g_sum_e[t] = a; g_sumsq_e[t] = b;
    } else {
        int c = t - 128;
        float a = 0.f, b = 0.f;
        for (int j = 0; j < 64; j++) { a += g_slabh[0][j][c]; b += g_slabh[1][j][c]; }
        g_sum_h[c] = a; g_sumsq_h[c] = b;
    }
}

// ---------------- outputs ------------------------------------------------------
__global__ void k_hout(const float* __restrict__ gamma, const float* __restrict__ beta,
                       float* __restrict__ out) {
    __shared__ float sM[DD], sS[DD], sB[DD];
    const int t = threadIdx.x;
    if (t < DD) {
        float mean = g_sum_h[t] * (1.f / NN);
        float var  = g_sumsq_h[t] * (1.f / NN) - mean * mean;
        sM[t] = mean; sS[t] = gamma[t] * rsqrtf(var + 1e-5f); sB[t] = beta[t];
    }
    __syncthreads();
    int i4 = blockIdx.x * 256 + t;
    if (i4 < NN * 32) {
        float4 x = ((const float4*)g_hnew)[i4];
        int c = (i4 & 31) * 4;
        float4 o;
        o.x = fmaxf(0.f, (x.x - sM[c+0]) * sS[c+0] + sB[c+0]);
        o.y = fmaxf(0.f, (x.y - sM[c+1]) * sS[c+1] + sB[c+1]);
        o.z = fmaxf(0.f, (x.z - sM[c+2]) * sS[c+2] + sB[c+2]);
        o.w = fmaxf(0.f, (x.w - sM[c+3]) * sS[c+3] + sB[c+3]);
        __stcs(&((float4*)out)[i4], o);
    }
}

__global__ void k_eout(const float* __restrict__ gamma, const float* __restrict__ beta,
                       float* __restrict__ out) {
    __shared__ float sM[DD], sS[DD], sB[DD];
    const int t = threadIdx.x;
    if (t < DD) {
        float mean = g_sum_e[t] * (1.f / NE);
        float var  = g_sumsq_e[t] * (1.f / NE) - mean * mean;
        sM[t] = mean; sS[t] = gamma[t] * rsqrtf(var + 1e-5f); sB[t] = beta[t];
    }
    __syncthreads();
    size_t i8 = (size_t)blockIdx.x * 256 + t;
    const __half2* xp = (const __half2*)(g_xh + i8 * 8);
    int c = (int)((i8 & 15) * 8);
    float* op = out + i8 * 8;
    float4 o0, o1;
    float2 v0 = __half22float2(__ldcs(&xp[0]));
    float2 v1 = __half22float2(__ldcs(&xp[1]));
    float2 v2 = __half22float2(__ldcs(&xp[2]));
    float2 v3 = __half22float2(__ldcs(&xp[3]));
    o0.x = fmaxf(0.f, (v0.x - sM[c+0]) * sS[c+0] + sB[c+0]);
    o0.y = fmaxf(0.f, (v0.y - sM[c+1]) * sS[c+1] + sB[c+1]);
    o0.z = fmaxf(0.f, (v1.x - sM[c+2]) * sS[c+2] + sB[c+2]);
    o0.w = fmaxf(0.f, (v1.y - sM[c+3]) * sS[c+3] + sB[c+3]);
    o1.x = fmaxf(0.f, (v2.x - sM[c+4]) * sS[c+4] + sB[c+4]);
    o1.y = fmaxf(0.f, (v2.y - sM[c+5]) * sS[c+5] + sB[c+5]);
    o1.z = fmaxf(0.f, (v3.x - sM[c+6]) * sS[c+6] + sB[c+6]);
    o1.w = fmaxf(0.f, (v3.y - sM[c+7]) * sS[c+7] + sB[c+7]);
    __stcs((float4*)(op), o0);
    __stcs((float4*)(op + 4), o1);
}

// ---------------- launch ------------------------------------------------------
extern "C" void kernel_launch(void* const* d_in, const int* in_sizes, int n_in,
                              void* d_out, int out_size) {
    const float* h   = (const float*)d_in[0];
    const float* e   = (const float*)d_in[1];
    const int*   src = (const int*)  d_in[2];
    const int*   dst = (const int*)  d_in[3];
    const float* WA  = (const float*)d_in[4];  const float* bA = (const float*)d_in[5];
    const float* WB  = (const float*)d_in[6];  const float* bB = (const float*)d_in[7];
    const float* WC  = (const float*)d_in[8];  const float* bC = (const float*)d_in[9];
    const float* WD  = (const float*)d_in[10]; const float* bD = (const float*)d_in[11];
    const float* WE  = (const float*)d_in[12]; const float* bE = (const float*)d_in[13];
    const float* gamma_h = (const float*)d_in[14]; const float* beta_h = (const float*)d_in[15];
    const float* gamma_e = (const float*)d_in[16]; const float* beta_e = (const float*)d_in[17];
    float* out = (float*)d_out;

    static cudaStream_t s1 = nullptr;
    static cudaEvent_t ev0 = nullptr, ev1 = nullptr, ev2 = nullptr, ev3 = nullptr;
    if (!s1) {
        cudaStreamCreateWithFlags(&s1, cudaStreamNonBlocking);
        cudaEventCreateWithFlags(&ev0, cudaEventDisableTiming);
        cudaEventCreateWithFlags(&ev1, cudaEventDisableTiming);
        cudaEventCreateWithFlags(&ev2, cudaEventDisableTiming);
        cudaEventCreateWithFlags(&ev3, cudaEventDisableTiming);
        cudaFuncSetAttribute(k_node_hmma, cudaFuncAttributeMaxDynamicSharedMemorySize, SM_NODE_TOTAL);
        cudaFuncSetAttribute(k_edge_hmma, cudaFuncAttributeMaxDynamicSharedMemorySize, SM_EDGE_TOTAL);
    }

    // k_edge_hmma stays 4th submitted (ncu capture slot)
    k_init<<<(NN + 255) / 256, 256>>>();                                   // 1
    k_prep_w<<<dim3(64, 5), 256>>>(WA, WB, WC, WD, WE);                    // 2
    cudaEventRecord(ev0, 0);
    cudaStreamWaitEvent(s1, ev0, 0);
    k_deg<<<(NE + 255) / 256, 256, 0, s1>>>(dst);                          // 3
    k_edge_hmma<<<EGRID, 512, SM_EDGE_TOTAL>>>(e, bC);                     // 4 <- profiled
    k_scan1<<<49, 1024, 0, s1>>>();
    k_scan2<<<1, 1, 0, s1>>>();
    k_scan3<<<(NN + 255) / 256, 256, 0, s1>>>();
    k_scatter<<<(NE + 255) / 256, 256, 0, s1>>>(src, dst);
    k_node_hmma<<<NT_NODE, 512, SM_NODE_TOTAL, s1>>>(h, bA, bB, bD, bE);
    cudaEventRecord(ev1, s1);

    cudaStreamWaitEvent(0, ev1, 0);
    k_gather<<<NN, 128>>>();
    k_red<<<1, 256>>>();
    cudaEventRecord(ev2, 0);

    cudaStreamWaitEvent(s1, ev2, 0);
    k_hout<<<(NN * 32 + 255) / 256, 256, 0, s1>>>(gamma_h, beta_h, out);
    cudaEventRecord(ev3, s1);

    k_eout<<<NE / 16, 256>>>(gamma_e, beta_e, out + (size_t)NN * DD);
    cudaStreamWaitEvent(0, ev3, 0);
}